// round 12
// baseline (speedup 1.0000x reference)
#include <cuda_runtime.h>
#include <math.h>

// Problem constants (fixed by the dataset)
#define T_TOK 8192      // B*N tokens
#define EMB   1024
#define HID   1536
#define NE    8
#define TOPK  2

// GEMM tiling
#define BM 128
#define BN 128
#define BK 8

// ---------------- device scratch (static: no allocations allowed) ----------
__device__ int   g_cnt[NE];                 // tokens per expert
__device__ int   g_off[NE];                 // exclusive scan of g_cnt
__device__ int   g_tok[NE * T_TOK];         // gathered token ids per expert
__device__ float g_h[(size_t)T_TOK * TOPK * HID];  // hidden activations (16384 x 1536)

// ---------------- kernel 1: zero output + reset counters -------------------
__global__ void zero_kernel(float4* __restrict__ out, int n4) {
    if (blockIdx.x == 0 && threadIdx.x < NE) g_cnt[threadIdx.x] = 0;
    int i = blockIdx.x * blockDim.x + threadIdx.x;
    float4 z = make_float4(0.f, 0.f, 0.f, 0.f);
    for (; i < n4; i += gridDim.x * blockDim.x) out[i] = z;
}

// ---------------- kernel 2: router (warp per token, top-2) -----------------
__global__ void router_kernel(const float* __restrict__ x,
                              const float* __restrict__ Wr,
                              const float* __restrict__ br) {
    int gw   = (blockIdx.x * blockDim.x + threadIdx.x) >> 5;
    int lane = threadIdx.x & 31;
    if (gw >= T_TOK) return;
    const float* xr = x + (size_t)gw * EMB;
    float acc[NE];
#pragma unroll
    for (int e = 0; e < NE; e++) acc[e] = 0.f;
    for (int j = lane; j < EMB; j += 32) {
        float xv = xr[j];
        const float4* w = (const float4*)(Wr + (size_t)j * NE);
        float4 w0 = w[0], w1 = w[1];
        acc[0] += xv * w0.x; acc[1] += xv * w0.y;
        acc[2] += xv * w0.z; acc[3] += xv * w0.w;
        acc[4] += xv * w1.x; acc[5] += xv * w1.y;
        acc[6] += xv * w1.z; acc[7] += xv * w1.w;
    }
#pragma unroll
    for (int e = 0; e < NE; e++) {
#pragma unroll
        for (int off = 16; off > 0; off >>= 1)
            acc[e] += __shfl_xor_sync(0xffffffffu, acc[e], off);
    }
    if (lane == 0) {
        float l[NE];
#pragma unroll
        for (int e = 0; e < NE; e++) l[e] = acc[e] + br[e];
        // top-1: strict > keeps lowest index on ties (matches jax top_k)
        int i1 = 0; float v1 = l[0];
#pragma unroll
        for (int e = 1; e < NE; e++) if (l[e] > v1) { v1 = l[e]; i1 = e; }
        int i2 = -1; float v2 = -3.4e38f;
#pragma unroll
        for (int e = 0; e < NE; e++)
            if (e != i1 && l[e] > v2) { v2 = l[e]; i2 = e; }
        int p1 = atomicAdd(&g_cnt[i1], 1); g_tok[i1 * T_TOK + p1] = gw;
        int p2 = atomicAdd(&g_cnt[i2], 1); g_tok[i2 * T_TOK + p2] = gw;
    }
}

// ---------------- kernel 3: exclusive scan of counts (tiny) ----------------
__global__ void offs_kernel() {
    if (blockIdx.x == 0 && threadIdx.x == 0) {
        int s = 0;
        for (int e = 0; e < NE; e++) { g_off[e] = s; s += g_cnt[e]; }
    }
}

__device__ __forceinline__ float gelu_exact(float v) {
    return 0.5f * v * (1.0f + erff(v * 0.70710678118654752440f));
}

// ---------------- kernel 4: grouped GEMM1  h = gelu(X_sel @ W1[e] + b1) ----
// grid: (T_TOK/BM, HID/BN, NE); block 256; 8x8 register micro-tile.
__global__ __launch_bounds__(256, 2) void gemm1_kernel(
        const float* __restrict__ x, const float* __restrict__ W1,
        const float* __restrict__ b1) {
    const int e  = blockIdx.z;
    const int M  = g_cnt[e];
    const int m0 = blockIdx.x * BM;
    if (m0 >= M) return;
    const int n0 = blockIdx.y * BN;

    __shared__ float As[BK][BM];
    __shared__ float Bs[BK][BN];

    const int tid = threadIdx.x;
    const int tx = tid & 15, ty = tid >> 4;

    // A (gathered x rows): 2 threads per row, float4 each
    int ar = tid >> 1;
    int ac = (tid & 1) * 4;
    int mi = m0 + ar; if (mi > M - 1) mi = M - 1;       // clamp; masked at store
    const float* aptr = x + (size_t)g_tok[e * T_TOK + mi] * EMB + ac;

    // B (W1[e], [E][H] row-major): 32 threads per k-row, float4 each
    int bk = tid >> 5;
    int bn = (tid & 31) * 4;
    const float* bptr = W1 + (size_t)e * EMB * HID + (size_t)bk * HID + n0 + bn;

    float acc[8][8];
#pragma unroll
    for (int i = 0; i < 8; i++)
#pragma unroll
        for (int j = 0; j < 8; j++) acc[i][j] = 0.f;

    for (int k0 = 0; k0 < EMB; k0 += BK) {
        float4 av = *(const float4*)(aptr + k0);
        float4 bv = *(const float4*)(bptr + (size_t)k0 * HID);
        __syncthreads();
        As[ac + 0][ar] = av.x; As[ac + 1][ar] = av.y;
        As[ac + 2][ar] = av.z; As[ac + 3][ar] = av.w;
        *(float4*)&Bs[bk][bn] = bv;
        __syncthreads();
#pragma unroll
        for (int kk = 0; kk < BK; kk++) {
            float4 a0 = *(const float4*)&As[kk][ty * 8];
            float4 a1 = *(const float4*)&As[kk][ty * 8 + 4];
            float4 b0 = *(const float4*)&Bs[kk][tx * 8];
            float4 b1f = *(const float4*)&Bs[kk][tx * 8 + 4];
            float a[8] = {a0.x, a0.y, a0.z, a0.w, a1.x, a1.y, a1.z, a1.w};
            float b[8] = {b0.x, b0.y, b0.z, b0.w, b1f.x, b1f.y, b1f.z, b1f.w};
#pragma unroll
            for (int i = 0; i < 8; i++)
#pragma unroll
                for (int j = 0; j < 8; j++) acc[i][j] += a[i] * b[j];
        }
    }

    const int base = g_off[e];
    float bb[8];
#pragma unroll
    for (int j = 0; j < 8; j++) bb[j] = b1[(size_t)e * HID + n0 + tx * 8 + j];
#pragma unroll
    for (int i = 0; i < 8; i++) {
        int m = m0 + ty * 8 + i;
        if (m < M) {
            float* dst = g_h + (size_t)(base + m) * HID + n0 + tx * 8;
            float v[8];
#pragma unroll
            for (int j = 0; j < 8; j++) v[j] = gelu_exact(acc[i][j] + bb[j]);
            *(float4*)dst       = make_float4(v[0], v[1], v[2], v[3]);
            *(float4*)(dst + 4) = make_float4(v[4], v[5], v[6], v[7]);
        }
    }
}

// ---------------- kernel 5: grouped GEMM2  out += 0.5*(h @ W2[e] + b2) -----
// grid: (T_TOK/BM, EMB/BN, NE); block 256.
__global__ __launch_bounds__(256, 2) void gemm2_kernel(
        const float* __restrict__ W2, const float* __restrict__ b2,
        float* __restrict__ out) {
    const int e  = blockIdx.z;
    const int M  = g_cnt[e];
    const int m0 = blockIdx.x * BM;
    if (m0 >= M) return;
    const int n0 = blockIdx.y * BN;
    const int base = g_off[e];

    __shared__ float As[BK][BM];
    __shared__ float Bs[BK][BN];

    const int tid = threadIdx.x;
    const int tx = tid & 15, ty = tid >> 4;

    int ar = tid >> 1;
    int ac = (tid & 1) * 4;
    int mi = m0 + ar; if (mi > M - 1) mi = M - 1;
    const float* aptr = g_h + (size_t)(base + mi) * HID + ac;

    int bk = tid >> 5;
    int bn = (tid & 31) * 4;
    const float* bptr = W2 + (size_t)e * HID * EMB + (size_t)bk * EMB + n0 + bn;

    float acc[8][8];
#pragma unroll
    for (int i = 0; i < 8; i++)
#pragma unroll
        for (int j = 0; j < 8; j++) acc[i][j] = 0.f;

    for (int k0 = 0; k0 < HID; k0 += BK) {
        float4 av = *(const float4*)(aptr + k0);
        float4 bv = *(const float4*)(bptr + (size_t)k0 * EMB);
        __syncthreads();
        As[ac + 0][ar] = av.x; As[ac + 1][ar] = av.y;
        As[ac + 2][ar] = av.z; As[ac + 3][ar] = av.w;
        *(float4*)&Bs[bk][bn] = bv;
        __syncthreads();
#pragma unroll
        for (int kk = 0; kk < BK; kk++) {
            float4 a0 = *(const float4*)&As[kk][ty * 8];
            float4 a1 = *(const float4*)&As[kk][ty * 8 + 4];
            float4 b0 = *(const float4*)&Bs[kk][tx * 8];
            float4 b1f = *(const float4*)&Bs[kk][tx * 8 + 4];
            float a[8] = {a0.x, a0.y, a0.z, a0.w, a1.x, a1.y, a1.z, a1.w};
            float b[8] = {b0.x, b0.y, b0.z, b0.w, b1f.x, b1f.y, b1f.z, b1f.w};
#pragma unroll
            for (int i = 0; i < 8; i++)
#pragma unroll
                for (int j = 0; j < 8; j++) acc[i][j] += a[i] * b[j];
        }
    }

    float bb[8];
#pragma unroll
    for (int j = 0; j < 8; j++) bb[j] = b2[(size_t)e * EMB + n0 + tx * 8 + j];
#pragma unroll
    for (int i = 0; i < 8; i++) {
        int m = m0 + ty * 8 + i;
        if (m < M) {
            int tok = g_tok[e * T_TOK + m];
            float* dst = out + (size_t)tok * EMB + n0 + tx * 8;
            // exactly 2 contributions per output element -> commutative -> deterministic
#pragma unroll
            for (int j = 0; j < 8; j++)
                atomicAdd(dst + j, 0.5f * (acc[i][j] + bb[j]));
        }
    }
}

// ---------------- launch ----------------------------------------------------
extern "C" void kernel_launch(void* const* d_in, const int* in_sizes, int n_in,
                              void* d_out, int out_size) {
    const float* x  = (const float*)d_in[0];
    const float* Wr = (const float*)d_in[1];
    const float* br = (const float*)d_in[2];
    const float* W1 = (const float*)d_in[3];
    const float* b1 = (const float*)d_in[4];
    const float* W2 = (const float*)d_in[5];
    const float* b2 = (const float*)d_in[6];
    // d_in[7] is k (fixed at 2 for this dataset)
    float* out = (float*)d_out;

    int n4 = out_size / 4;  // out is fp32, out_size % 4 == 0 (T*E)
    zero_kernel<<<(n4 + 255) / 256, 256>>>((float4*)out, n4);
    router_kernel<<<T_TOK / 8, 256>>>(x, Wr, br);
    offs_kernel<<<1, 32>>>();
    gemm1_kernel<<<dim3(T_TOK / BM, HID / BN, NE), 256>>>(x, W1, b1);
    gemm2_kernel<<<dim3(T_TOK / BM, EMB / BN, NE), 256>>>(W2, b2, out);
}

// round 13
// speedup vs baseline: 1.0017x; 1.0017x over previous
#include <cuda_runtime.h>
#include <math.h>

// Problem constants (fixed by the dataset)
#define T_TOK 8192      // B*N tokens
#define EMB   1024
#define HID   1536
#define NE    8
#define TOPK  2

// GEMM tiling
#define BM 128
#define BN 128
#define BK 8

// ---------------- device scratch (static: no allocations allowed) ----------
__device__ int   g_cnt[NE];                 // tokens per expert
__device__ int   g_off[NE];                 // exclusive scan of g_cnt
__device__ int   g_tok[NE * T_TOK];         // gathered token ids per expert
__device__ float g_h[(size_t)T_TOK * TOPK * HID];  // hidden activations (16384 x 1536)

// ---------------- kernel 1: zero output + reset counters -------------------
__global__ void zero_kernel(float4* __restrict__ out, int n4) {
    if (blockIdx.x == 0 && threadIdx.x < NE) g_cnt[threadIdx.x] = 0;
    int i = blockIdx.x * blockDim.x + threadIdx.x;
    float4 z = make_float4(0.f, 0.f, 0.f, 0.f);
    for (; i < n4; i += gridDim.x * blockDim.x) out[i] = z;
}

// ---------------- kernel 2: router (warp per token, top-2) -----------------
__global__ void router_kernel(const float* __restrict__ x,
                              const float* __restrict__ Wr,
                              const float* __restrict__ br) {
    int gw   = (blockIdx.x * blockDim.x + threadIdx.x) >> 5;
    int lane = threadIdx.x & 31;
    if (gw >= T_TOK) return;
    const float* xr = x + (size_t)gw * EMB;
    float acc[NE];
#pragma unroll
    for (int e = 0; e < NE; e++) acc[e] = 0.f;
    for (int j = lane; j < EMB; j += 32) {
        float xv = xr[j];
        const float4* w = (const float4*)(Wr + (size_t)j * NE);
        float4 w0 = w[0], w1 = w[1];
        acc[0] += xv * w0.x; acc[1] += xv * w0.y;
        acc[2] += xv * w0.z; acc[3] += xv * w0.w;
        acc[4] += xv * w1.x; acc[5] += xv * w1.y;
        acc[6] += xv * w1.z; acc[7] += xv * w1.w;
    }
#pragma unroll
    for (int e = 0; e < NE; e++) {
#pragma unroll
        for (int off = 16; off > 0; off >>= 1)
            acc[e] += __shfl_xor_sync(0xffffffffu, acc[e], off);
    }
    if (lane == 0) {
        float l[NE];
#pragma unroll
        for (int e = 0; e < NE; e++) l[e] = acc[e] + br[e];
        // top-1: strict > keeps lowest index on ties (matches jax top_k)
        int i1 = 0; float v1 = l[0];
#pragma unroll
        for (int e = 1; e < NE; e++) if (l[e] > v1) { v1 = l[e]; i1 = e; }
        int i2 = -1; float v2 = -3.4e38f;
#pragma unroll
        for (int e = 0; e < NE; e++)
            if (e != i1 && l[e] > v2) { v2 = l[e]; i2 = e; }
        int p1 = atomicAdd(&g_cnt[i1], 1); g_tok[i1 * T_TOK + p1] = gw;
        int p2 = atomicAdd(&g_cnt[i2], 1); g_tok[i2 * T_TOK + p2] = gw;
    }
}

// ---------------- kernel 3: exclusive scan of counts (tiny) ----------------
__global__ void offs_kernel() {
    if (blockIdx.x == 0 && threadIdx.x == 0) {
        int s = 0;
        for (int e = 0; e < NE; e++) { g_off[e] = s; s += g_cnt[e]; }
    }
}

__device__ __forceinline__ float gelu_exact(float v) {
    return 0.5f * v * (1.0f + erff(v * 0.70710678118654752440f));
}

// ---------------- kernel 4: grouped GEMM1  h = gelu(X_sel @ W1[e] + b1) ----
// grid: (T_TOK/BM, HID/BN, NE); block 256; 8x8 register micro-tile.
__global__ __launch_bounds__(256, 2) void gemm1_kernel(
        const float* __restrict__ x, const float* __restrict__ W1,
        const float* __restrict__ b1) {
    const int e  = blockIdx.z;
    const int M  = g_cnt[e];
    const int m0 = blockIdx.x * BM;
    if (m0 >= M) return;
    const int n0 = blockIdx.y * BN;

    __shared__ float As[BK][BM];
    __shared__ float Bs[BK][BN];

    const int tid = threadIdx.x;
    const int tx = tid & 15, ty = tid >> 4;

    // A (gathered x rows): 2 threads per row, float4 each
    int ar = tid >> 1;
    int ac = (tid & 1) * 4;
    int mi = m0 + ar; if (mi > M - 1) mi = M - 1;       // clamp; masked at store
    const float* aptr = x + (size_t)g_tok[e * T_TOK + mi] * EMB + ac;

    // B (W1[e], [E][H] row-major): 32 threads per k-row, float4 each
    int bk = tid >> 5;
    int bn = (tid & 31) * 4;
    const float* bptr = W1 + (size_t)e * EMB * HID + (size_t)bk * HID + n0 + bn;

    float acc[8][8];
#pragma unroll
    for (int i = 0; i < 8; i++)
#pragma unroll
        for (int j = 0; j < 8; j++) acc[i][j] = 0.f;

    for (int k0 = 0; k0 < EMB; k0 += BK) {
        float4 av = *(const float4*)(aptr + k0);
        float4 bv = *(const float4*)(bptr + (size_t)k0 * HID);
        __syncthreads();
        As[ac + 0][ar] = av.x; As[ac + 1][ar] = av.y;
        As[ac + 2][ar] = av.z; As[ac + 3][ar] = av.w;
        *(float4*)&Bs[bk][bn] = bv;
        __syncthreads();
#pragma unroll
        for (int kk = 0; kk < BK; kk++) {
            float4 a0 = *(const float4*)&As[kk][ty * 8];
            float4 a1 = *(const float4*)&As[kk][ty * 8 + 4];
            float4 b0 = *(const float4*)&Bs[kk][tx * 8];
            float4 b1f = *(const float4*)&Bs[kk][tx * 8 + 4];
            float a[8] = {a0.x, a0.y, a0.z, a0.w, a1.x, a1.y, a1.z, a1.w};
            float b[8] = {b0.x, b0.y, b0.z, b0.w, b1f.x, b1f.y, b1f.z, b1f.w};
#pragma unroll
            for (int i = 0; i < 8; i++)
#pragma unroll
                for (int j = 0; j < 8; j++) acc[i][j] += a[i] * b[j];
        }
    }

    const int base = g_off[e];
    float bb[8];
#pragma unroll
    for (int j = 0; j < 8; j++) bb[j] = b1[(size_t)e * HID + n0 + tx * 8 + j];
#pragma unroll
    for (int i = 0; i < 8; i++) {
        int m = m0 + ty * 8 + i;
        if (m < M) {
            float* dst = g_h + (size_t)(base + m) * HID + n0 + tx * 8;
            float v[8];
#pragma unroll
            for (int j = 0; j < 8; j++) v[j] = gelu_exact(acc[i][j] + bb[j]);
            *(float4*)dst       = make_float4(v[0], v[1], v[2], v[3]);
            *(float4*)(dst + 4) = make_float4(v[4], v[5], v[6], v[7]);
        }
    }
}

// ---------------- kernel 5: grouped GEMM2  out += 0.5*(h @ W2[e] + b2) -----
// grid: (T_TOK/BM, EMB/BN, NE); block 256.
__global__ __launch_bounds__(256, 2) void gemm2_kernel(
        const float* __restrict__ W2, const float* __restrict__ b2,
        float* __restrict__ out) {
    const int e  = blockIdx.z;
    const int M  = g_cnt[e];
    const int m0 = blockIdx.x * BM;
    if (m0 >= M) return;
    const int n0 = blockIdx.y * BN;
    const int base = g_off[e];

    __shared__ float As[BK][BM];
    __shared__ float Bs[BK][BN];

    const int tid = threadIdx.x;
    const int tx = tid & 15, ty = tid >> 4;

    int ar = tid >> 1;
    int ac = (tid & 1) * 4;
    int mi = m0 + ar; if (mi > M - 1) mi = M - 1;
    const float* aptr = g_h + (size_t)(base + mi) * HID + ac;

    int bk = tid >> 5;
    int bn = (tid & 31) * 4;
    const float* bptr = W2 + (size_t)e * HID * EMB + (size_t)bk * EMB + n0 + bn;

    float acc[8][8];
#pragma unroll
    for (int i = 0; i < 8; i++)
#pragma unroll
        for (int j = 0; j < 8; j++) acc[i][j] = 0.f;

    for (int k0 = 0; k0 < HID; k0 += BK) {
        float4 av = *(const float4*)(aptr + k0);
        float4 bv = *(const float4*)(bptr + (size_t)k0 * EMB);
        __syncthreads();
        As[ac + 0][ar] = av.x; As[ac + 1][ar] = av.y;
        As[ac + 2][ar] = av.z; As[ac + 3][ar] = av.w;
        *(float4*)&Bs[bk][bn] = bv;
        __syncthreads();
#pragma unroll
        for (int kk = 0; kk < BK; kk++) {
            float4 a0 = *(const float4*)&As[kk][ty * 8];
            float4 a1 = *(const float4*)&As[kk][ty * 8 + 4];
            float4 b0 = *(const float4*)&Bs[kk][tx * 8];
            float4 b1f = *(const float4*)&Bs[kk][tx * 8 + 4];
            float a[8] = {a0.x, a0.y, a0.z, a0.w, a1.x, a1.y, a1.z, a1.w};
            float b[8] = {b0.x, b0.y, b0.z, b0.w, b1f.x, b1f.y, b1f.z, b1f.w};
#pragma unroll
            for (int i = 0; i < 8; i++)
#pragma unroll
                for (int j = 0; j < 8; j++) acc[i][j] += a[i] * b[j];
        }
    }

    float bb[8];
#pragma unroll
    for (int j = 0; j < 8; j++) bb[j] = b2[(size_t)e * EMB + n0 + tx * 8 + j];
#pragma unroll
    for (int i = 0; i < 8; i++) {
        int m = m0 + ty * 8 + i;
        if (m < M) {
            int tok = g_tok[e * T_TOK + m];
            float* dst = out + (size_t)tok * EMB + n0 + tx * 8;
            // exactly 2 contributions per output element -> commutative -> deterministic
#pragma unroll
            for (int j = 0; j < 8; j++)
                atomicAdd(dst + j, 0.5f * (acc[i][j] + bb[j]));
        }
    }
}

// ---------------- launch ----------------------------------------------------
extern "C" void kernel_launch(void* const* d_in, const int* in_sizes, int n_in,
                              void* d_out, int out_size) {
    const float* x  = (const float*)d_in[0];
    const float* Wr = (const float*)d_in[1];
    const float* br = (const float*)d_in[2];
    const float* W1 = (const float*)d_in[3];
    const float* b1 = (const float*)d_in[4];
    const float* W2 = (const float*)d_in[5];
    const float* b2 = (const float*)d_in[6];
    // d_in[7] is k (fixed at 2 for this dataset)
    float* out = (float*)d_out;

    int n4 = out_size / 4;  // out is fp32, out_size % 4 == 0 (T*E)
    zero_kernel<<<(n4 + 255) / 256, 256>>>((float4*)out, n4);
    router_kernel<<<T_TOK / 8, 256>>>(x, Wr, br);
    offs_kernel<<<1, 32>>>();
    gemm1_kernel<<<dim3(T_TOK / BM, HID / BN, NE), 256>>>(x, W1, b1);
    gemm2_kernel<<<dim3(T_TOK / BM, EMB / BN, NE), 256>>>(W2, b2, out);
}

// round 16
// speedup vs baseline: 2.2819x; 2.2780x over previous
#include <cuda_runtime.h>
#include <math.h>
#include <stdint.h>

// Problem constants
#define T_TOK 8192
#define EMB   1024
#define HID   1536
#define NE    8

// GEMM tiling
#define BM 128
#define BN 128
#define BK 32
#define NSTAGE 3
#define PAD_ROW 36                         // floats per smem tile row (32 + 4 pad)
#define A_BYTES (BM * PAD_ROW * 4)         // 18432
#define STAGE_BYTES (2 * A_BYTES)          // 36864 (A tile + B tile)
#define GEMM_SMEM (NSTAGE * STAGE_BYTES)   // 110592

// ---------------- static device scratch ------------------------------------
__device__ int   g_cnt[NE];
__device__ int   g_off[NE];
__device__ int   g_tok[NE*T_TOK];
__device__ int   g_pe[T_TOK*2];
__device__ int   g_pp[T_TOK*2];
__device__ float g_xc [(size_t)T_TOK*EMB];        // tf32-rounded x
__device__ float g_h  [(size_t)T_TOK*2*HID];      // hidden acts (tf32-rounded)
__device__ float g_y  [(size_t)T_TOK*2*EMB];      // expert outputs
__device__ float g_w1t[(size_t)NE*HID*EMB];       // W1^T K-major, tf32-rounded
__device__ float g_w2t[(size_t)NE*EMB*HID];       // W2^T K-major, tf32-rounded

// ---------------- PTX helpers ----------------------------------------------
__device__ __forceinline__ uint32_t s2u(const void* p) {
    uint32_t a;
    asm("{ .reg .u64 t; cvta.to.shared.u64 t, %1; cvt.u32.u64 %0, t; }"
        : "=r"(a) : "l"(p));
    return a;
}
__device__ __forceinline__ float to_tf32(float v) {
    asm("cvt.rna.tf32.f32 %0, %1;" : "=f"(v) : "f"(v));
    return v;
}
__device__ __forceinline__ void cp16(uint32_t dst, const void* src) {
    asm volatile("cp.async.cg.shared.global [%0], [%1], 16;" :: "r"(dst), "l"(src));
}
#define CP_COMMIT() asm volatile("cp.async.commit_group;" ::: "memory")
template<int N> __device__ __forceinline__ void cp_wait() {
    asm volatile("cp.async.wait_group %0;" :: "n"(N) : "memory");
}
__device__ __forceinline__ void mma_tf32(float* d, const uint32_t* a, const uint32_t* b) {
    asm volatile(
        "mma.sync.aligned.m16n8k8.row.col.f32.tf32.tf32.f32 "
        "{%0,%1,%2,%3}, {%4,%5,%6,%7}, {%8,%9}, {%0,%1,%2,%3};"
        : "+f"(d[0]), "+f"(d[1]), "+f"(d[2]), "+f"(d[3])
        : "r"(a[0]), "r"(a[1]), "r"(a[2]), "r"(a[3]), "r"(b[0]), "r"(b[1]));
}

// ---------------- kernel: round x to tf32 + reset counters -----------------
__global__ void prep_x_kernel(const float4* __restrict__ x, int n4) {
    if (blockIdx.x == 0 && threadIdx.x < NE) g_cnt[threadIdx.x] = 0;
    for (int i = blockIdx.x * blockDim.x + threadIdx.x; i < n4;
         i += gridDim.x * blockDim.x) {
        float4 v = x[i];
        v.x = to_tf32(v.x); v.y = to_tf32(v.y);
        v.z = to_tf32(v.z); v.w = to_tf32(v.w);
        ((float4*)g_xc)[i] = v;
    }
}

// ---------------- kernel: per-expert transpose + tf32 round ----------------
// src [NE][R][C] -> dst [NE][C][R]; grid (C/32, R/32, NE), block (32,8).
// CRITICAL: dst is a __device__ global referenced from DEVICE code via the
// template switch. Passing the global as a host-side kernel argument resolves
// to the host shadow symbol (silently writable via GB300 ATS) — that was the
// R15 bug that left g_w1t/g_w2t all-zero.
template<int WHICH>   // 0 -> g_w1t, 1 -> g_w2t
__global__ void transpose_kernel(const float* __restrict__ src, int R, int C) {
    __shared__ float t[32][33];
    float* __restrict__ dstg = (WHICH == 0) ? g_w1t : g_w2t;
    int e = blockIdx.z;
    const float* s = src  + (size_t)e * R * C;
    float*       d = dstg + (size_t)e * R * C;
    int c0 = blockIdx.x * 32, r0 = blockIdx.y * 32;
    int tx = threadIdx.x, ty = threadIdx.y;
#pragma unroll
    for (int i = 0; i < 4; i++)
        t[ty + 8*i][tx] = s[(size_t)(r0 + ty + 8*i) * C + c0 + tx];
    __syncthreads();
#pragma unroll
    for (int i = 0; i < 4; i++)
        d[(size_t)(c0 + ty + 8*i) * R + r0 + tx] = to_tf32(t[tx][ty + 8*i]);
}

// ---------------- kernel: router (warp per token, top-2) -------------------
__global__ void router_kernel(const float* __restrict__ x,
                              const float* __restrict__ Wr,
                              const float* __restrict__ br) {
    int gw   = (blockIdx.x * blockDim.x + threadIdx.x) >> 5;
    int lane = threadIdx.x & 31;
    if (gw >= T_TOK) return;
    const float* xr = x + (size_t)gw * EMB;
    float acc[NE];
#pragma unroll
    for (int e = 0; e < NE; e++) acc[e] = 0.f;
    for (int j = lane; j < EMB; j += 32) {
        float xv = xr[j];
        const float4* w = (const float4*)(Wr + (size_t)j * NE);
        float4 w0 = w[0], w1 = w[1];
        acc[0] += xv * w0.x; acc[1] += xv * w0.y;
        acc[2] += xv * w0.z; acc[3] += xv * w0.w;
        acc[4] += xv * w1.x; acc[5] += xv * w1.y;
        acc[6] += xv * w1.z; acc[7] += xv * w1.w;
    }
#pragma unroll
    for (int e = 0; e < NE; e++) {
#pragma unroll
        for (int off = 16; off > 0; off >>= 1)
            acc[e] += __shfl_xor_sync(0xffffffffu, acc[e], off);
    }
    if (lane == 0) {
        float l[NE];
#pragma unroll
        for (int e = 0; e < NE; e++) l[e] = acc[e] + br[e];
        int i1 = 0; float v1 = l[0];
#pragma unroll
        for (int e = 1; e < NE; e++) if (l[e] > v1) { v1 = l[e]; i1 = e; }
        int i2 = -1; float v2 = -3.4e38f;
#pragma unroll
        for (int e = 0; e < NE; e++)
            if (e != i1 && l[e] > v2) { v2 = l[e]; i2 = e; }
        int p1 = atomicAdd(&g_cnt[i1], 1); g_tok[i1 * T_TOK + p1] = gw;
        int p2 = atomicAdd(&g_cnt[i2], 1); g_tok[i2 * T_TOK + p2] = gw;
        g_pe[2*gw] = i1; g_pp[2*gw] = p1;
        g_pe[2*gw+1] = i2; g_pp[2*gw+1] = p2;
    }
}

__global__ void offs_kernel() {
    if (blockIdx.x == 0 && threadIdx.x == 0) {
        int s = 0;
        for (int e = 0; e < NE; e++) { g_off[e] = s; s += g_cnt[e]; }
    }
}

__device__ __forceinline__ float gelu_exact(float v) {
    return 0.5f * v * (1.0f + erff(v * 0.70710678118654752440f));
}

// ---------------- tf32 mma.sync grouped GEMM -------------------------------
// CTA 128x128xBK, 8 warps (2x4), warp tile 64x32, m16n8k8 fragments.
// IS_G1: A = gathered g_xc rows, epilogue gelu(+b1)+tf32round -> g_h
// else : A = g_h rows,           epilogue raw                 -> g_y
template<int KTOT, bool IS_G1>
__global__ __launch_bounds__(256, 1) void gemm_tc(const float* __restrict__ bias_g) {
    const int e  = blockIdx.z;
    const int M  = g_cnt[e];
    const int m0 = blockIdx.x * BM;
    if (m0 >= M) return;
    const int n0   = blockIdx.y * BN;
    const int base = g_off[e];

    extern __shared__ __align__(128) char smem[];
    __shared__ float bias_s[BN];
    const uint32_t sb = s2u(smem);

    const int tid  = threadIdx.x;
    const int wid  = tid >> 5;
    const int lane = tid & 31;
    const int wm   = wid >> 2;            // 0..1 (m)
    const int wn   = wid & 3;             // 0..3 (n)
    const int ra   = lane >> 2;           // 0..7  (groupID)
    const int ca   = lane & 3;            // 0..3  (threadID_in_group)

    if (IS_G1 && tid < BN)
        bias_s[tid] = bias_g[(size_t)e * HID + n0 + tid];

    // g2s mapping: 2 threads per row, 4x16B chunks each (A and B same shape)
    const int arow = tid >> 1;
    const int aseg = tid & 1;
    int ami = m0 + arow; if (ami > M - 1) ami = M - 1;   // clamp; masked at store
    const float* asrc;
    if (IS_G1) asrc = g_xc + (size_t)g_tok[e * T_TOK + ami] * EMB + aseg * 16;
    else       asrc = g_h  + (size_t)(base + ami) * HID + aseg * 16;
    const float* bsrc;
    if (IS_G1) bsrc = g_w1t + ((size_t)e * HID + n0 + arow) * (size_t)EMB + aseg * 16;
    else       bsrc = g_w2t + ((size_t)e * EMB + n0 + arow) * (size_t)HID + aseg * 16;

    const uint32_t dbase = arow * (PAD_ROW * 4) + aseg * 64;

#define LOAD_STAGE(kt_, s_) do {                                          \
        uint32_t st_ = sb + (s_) * STAGE_BYTES;                           \
        const float* as_ = asrc + (kt_) * BK;                             \
        const float* bs_ = bsrc + (kt_) * BK;                             \
        _Pragma("unroll")                                                 \
        for (int j_ = 0; j_ < 4; j_++)                                    \
            cp16(st_ + dbase + j_ * 16, as_ + j_ * 4);                    \
        _Pragma("unroll")                                                 \
        for (int j_ = 0; j_ < 4; j_++)                                    \
            cp16(st_ + A_BYTES + dbase + j_ * 16, bs_ + j_ * 4);          \
        CP_COMMIT();                                                      \
    } while (0)

    float acc[4][4][4];
#pragma unroll
    for (int mt = 0; mt < 4; mt++)
#pragma unroll
        for (int nt = 0; nt < 4; nt++)
#pragma unroll
            for (int q = 0; q < 4; q++) acc[mt][nt][q] = 0.f;

    const int NK = KTOT / BK;
    LOAD_STAGE(0, 0);
    LOAD_STAGE(1, 1);

    for (int kt = 0; kt < NK; kt++) {
        const int cur = kt % NSTAGE;
        if (kt == NK - 1) cp_wait<0>(); else cp_wait<1>();
        __syncthreads();
        const int pf = kt + NSTAGE - 1;
        if (pf < NK) LOAD_STAGE(pf, pf % NSTAGE);

        const float* As = (const float*)(smem + cur * STAGE_BYTES);
        const float* Bs = (const float*)(smem + cur * STAGE_BYTES + A_BYTES);
#pragma unroll
        for (int kk = 0; kk < BK / 8; kk++) {
            uint32_t af[4][4];
#pragma unroll
            for (int mt = 0; mt < 4; mt++) {
                const float* p = As + (wm * 64 + mt * 16 + ra) * PAD_ROW + kk * 8 + ca;
                af[mt][0] = __float_as_uint(p[0]);
                af[mt][1] = __float_as_uint(p[8 * PAD_ROW]);
                af[mt][2] = __float_as_uint(p[4]);
                af[mt][3] = __float_as_uint(p[8 * PAD_ROW + 4]);
            }
            uint32_t bf[4][2];
#pragma unroll
            for (int nt = 0; nt < 4; nt++) {
                const float* p = Bs + (wn * 32 + nt * 8 + ra) * PAD_ROW + kk * 8 + ca;
                bf[nt][0] = __float_as_uint(p[0]);
                bf[nt][1] = __float_as_uint(p[4]);
            }
#pragma unroll
            for (int mt = 0; mt < 4; mt++)
#pragma unroll
                for (int nt = 0; nt < 4; nt++)
                    mma_tf32(acc[mt][nt], af[mt], bf[nt]);
        }
    }
#undef LOAD_STAGE

    // epilogue: acc[mt][nt] -> rows m0+wm*64+mt*16+ra(+8), cols n0+wn*32+nt*8+ca*2(+1)
#pragma unroll
    for (int mt = 0; mt < 4; mt++) {
#pragma unroll
        for (int half = 0; half < 2; half++) {
            const int m = m0 + wm * 64 + mt * 16 + ra + half * 8;
            if (m < M) {
                float* drow;
                if (IS_G1) drow = g_h + (size_t)(base + m) * HID + n0;
                else       drow = g_y + (size_t)(base + m) * EMB + n0;
#pragma unroll
                for (int nt = 0; nt < 4; nt++) {
                    const int c = wn * 32 + nt * 8 + ca * 2;
                    float v0 = acc[mt][nt][half * 2 + 0];
                    float v1 = acc[mt][nt][half * 2 + 1];
                    if (IS_G1) {
                        v0 = to_tf32(gelu_exact(v0 + bias_s[c]));
                        v1 = to_tf32(gelu_exact(v1 + bias_s[c + 1]));
                    }
                    *(float2*)(drow + c) = make_float2(v0, v1);
                }
            }
        }
    }
}

// ---------------- combine: out[t] = 0.5*(y[e1]+b2[e1] + y[e2]+b2[e2]) ------
__global__ void combine_kernel(const float* __restrict__ b2, float4* __restrict__ out) {
    int t  = blockIdx.x;
    int e1 = g_pe[2*t],     e2 = g_pe[2*t + 1];
    int r1 = g_off[e1] + g_pp[2*t];
    int r2 = g_off[e2] + g_pp[2*t + 1];
    const float4* y1 = (const float4*)(g_y + (size_t)r1 * EMB);
    const float4* y2 = (const float4*)(g_y + (size_t)r2 * EMB);
    const float4* c1 = (const float4*)(b2 + (size_t)e1 * EMB);
    const float4* c2 = (const float4*)(b2 + (size_t)e2 * EMB);
    float4* o = out + (size_t)t * (EMB / 4);
    int i = threadIdx.x;                       // EMB/4 == 256 == blockDim
    float4 a = y1[i], b = y2[i], p = c1[i], q = c2[i];
    o[i] = make_float4(0.5f * (a.x + b.x + p.x + q.x),
                       0.5f * (a.y + b.y + p.y + q.y),
                       0.5f * (a.z + b.z + p.z + q.z),
                       0.5f * (a.w + b.w + p.w + q.w));
}

// ---------------- launch ----------------------------------------------------
extern "C" void kernel_launch(void* const* d_in, const int* in_sizes, int n_in,
                              void* d_out, int out_size) {
    const float* x  = (const float*)d_in[0];
    const float* Wr = (const float*)d_in[1];
    const float* br = (const float*)d_in[2];
    const float* W1 = (const float*)d_in[3];
    const float* b1 = (const float*)d_in[4];
    const float* W2 = (const float*)d_in[5];
    const float* b2 = (const float*)d_in[6];
    float* out = (float*)d_out;

    // Not a stream op — safe under graph capture; called unconditionally
    // (no static guards per harness rules).
    cudaFuncSetAttribute(gemm_tc<EMB, true>,
                         cudaFuncAttributeMaxDynamicSharedMemorySize, GEMM_SMEM);
    cudaFuncSetAttribute(gemm_tc<HID, false>,
                         cudaFuncAttributeMaxDynamicSharedMemorySize, GEMM_SMEM);

    prep_x_kernel<<<2048, 256>>>((const float4*)x, T_TOK * EMB / 4);
    transpose_kernel<0><<<dim3(HID/32, EMB/32, NE), dim3(32, 8)>>>(W1, EMB, HID);
    transpose_kernel<1><<<dim3(EMB/32, HID/32, NE), dim3(32, 8)>>>(W2, HID, EMB);
    router_kernel<<<T_TOK / 8, 256>>>(x, Wr, br);
    offs_kernel<<<1, 32>>>();
    gemm_tc<EMB, true ><<<dim3(T_TOK/BM, HID/BN, NE), 256, GEMM_SMEM>>>(b1);
    gemm_tc<HID, false><<<dim3(T_TOK/BM, EMB/BN, NE), 256, GEMM_SMEM>>>(b2);
    combine_kernel<<<T_TOK, 256>>>(b2, (float4*)out);
}

// round 17
// speedup vs baseline: 2.8097x; 1.2313x over previous
#include <cuda_runtime.h>
#include <math.h>
#include <stdint.h>

// Problem constants
#define T_TOK 8192
#define EMB   1024
#define HID   1536
#define NE    8

// GEMM tiling
#define BM 128
#define BN 128
#define BK 16
#define NSTAGE 4
#define PAD_ROW 20                         // floats per smem tile row (16 + 4 pad)
#define A_BYTES (BM * PAD_ROW * 4)         // 10240
#define STAGE_BYTES (2 * A_BYTES)          // 20480 (A tile + B tile)
#define GEMM_SMEM (NSTAGE * STAGE_BYTES)   // 81920 -> 2 CTAs/SM

// ---------------- static device scratch ------------------------------------
__device__ int   g_cnt[NE];
__device__ int   g_off[NE];
__device__ int   g_tok[NE*T_TOK];
__device__ int   g_pe[T_TOK*2];
__device__ int   g_pp[T_TOK*2];
__device__ float g_xc [(size_t)T_TOK*EMB];        // tf32-rounded x
__device__ float g_h  [(size_t)T_TOK*2*HID];      // hidden acts (tf32-rounded)
__device__ float g_y  [(size_t)T_TOK*2*EMB];      // expert outputs
__device__ float g_w1t[(size_t)NE*HID*EMB];       // W1^T K-major, tf32-rounded
__device__ float g_w2t[(size_t)NE*EMB*HID];       // W2^T K-major, tf32-rounded

// ---------------- PTX helpers ----------------------------------------------
__device__ __forceinline__ uint32_t s2u(const void* p) {
    uint32_t a;
    asm("{ .reg .u64 t; cvta.to.shared.u64 t, %1; cvt.u32.u64 %0, t; }"
        : "=r"(a) : "l"(p));
    return a;
}
__device__ __forceinline__ float to_tf32(float v) {
    asm("cvt.rna.tf32.f32 %0, %1;" : "=f"(v) : "f"(v));
    return v;
}
__device__ __forceinline__ void cp16(uint32_t dst, const void* src) {
    asm volatile("cp.async.cg.shared.global [%0], [%1], 16;" :: "r"(dst), "l"(src));
}
#define CP_COMMIT() asm volatile("cp.async.commit_group;" ::: "memory")
template<int N> __device__ __forceinline__ void cp_wait() {
    asm volatile("cp.async.wait_group %0;" :: "n"(N) : "memory");
}
__device__ __forceinline__ void mma_tf32(float* d, const uint32_t* a, const uint32_t* b) {
    asm volatile(
        "mma.sync.aligned.m16n8k8.row.col.f32.tf32.tf32.f32 "
        "{%0,%1,%2,%3}, {%4,%5,%6,%7}, {%8,%9}, {%0,%1,%2,%3};"
        : "+f"(d[0]), "+f"(d[1]), "+f"(d[2]), "+f"(d[3])
        : "r"(a[0]), "r"(a[1]), "r"(a[2]), "r"(a[3]), "r"(b[0]), "r"(b[1]));
}

// ---------------- kernel: round x to tf32 + reset counters -----------------
__global__ void prep_x_kernel(const float4* __restrict__ x, int n4) {
    if (blockIdx.x == 0 && threadIdx.x < NE) g_cnt[threadIdx.x] = 0;
    for (int i = blockIdx.x * blockDim.x + threadIdx.x; i < n4;
         i += gridDim.x * blockDim.x) {
        float4 v = x[i];
        v.x = to_tf32(v.x); v.y = to_tf32(v.y);
        v.z = to_tf32(v.z); v.w = to_tf32(v.w);
        ((float4*)g_xc)[i] = v;
    }
}

// ---------------- kernel: per-expert transpose + tf32 round ----------------
// dst is a __device__ global referenced from DEVICE code via the template
// switch (host-passed globals resolve to the host shadow symbol — R15 bug).
template<int WHICH>   // 0 -> g_w1t, 1 -> g_w2t
__global__ void transpose_kernel(const float* __restrict__ src, int R, int C) {
    __shared__ float t[32][33];
    float* __restrict__ dstg = (WHICH == 0) ? g_w1t : g_w2t;
    int e = blockIdx.z;
    const float* s = src  + (size_t)e * R * C;
    float*       d = dstg + (size_t)e * R * C;
    int c0 = blockIdx.x * 32, r0 = blockIdx.y * 32;
    int tx = threadIdx.x, ty = threadIdx.y;
#pragma unroll
    for (int i = 0; i < 4; i++)
        t[ty + 8*i][tx] = s[(size_t)(r0 + ty + 8*i) * C + c0 + tx];
    __syncthreads();
#pragma unroll
    for (int i = 0; i < 4; i++)
        d[(size_t)(c0 + ty + 8*i) * R + r0 + tx] = to_tf32(t[tx][ty + 8*i]);
}

// ---------------- kernel: router (warp per token, top-2) -------------------
__global__ void router_kernel(const float* __restrict__ x,
                              const float* __restrict__ Wr,
                              const float* __restrict__ br) {
    int gw   = (blockIdx.x * blockDim.x + threadIdx.x) >> 5;
    int lane = threadIdx.x & 31;
    if (gw >= T_TOK) return;
    const float* xr = x + (size_t)gw * EMB;
    float acc[NE];
#pragma unroll
    for (int e = 0; e < NE; e++) acc[e] = 0.f;
    for (int j = lane; j < EMB; j += 32) {
        float xv = xr[j];
        const float4* w = (const float4*)(Wr + (size_t)j * NE);
        float4 w0 = w[0], w1 = w[1];
        acc[0] += xv * w0.x; acc[1] += xv * w0.y;
        acc[2] += xv * w0.z; acc[3] += xv * w0.w;
        acc[4] += xv * w1.x; acc[5] += xv * w1.y;
        acc[6] += xv * w1.z; acc[7] += xv * w1.w;
    }
#pragma unroll
    for (int e = 0; e < NE; e++) {
#pragma unroll
        for (int off = 16; off > 0; off >>= 1)
            acc[e] += __shfl_xor_sync(0xffffffffu, acc[e], off);
    }
    if (lane == 0) {
        float l[NE];
#pragma unroll
        for (int e = 0; e < NE; e++) l[e] = acc[e] + br[e];
        int i1 = 0; float v1 = l[0];
#pragma unroll
        for (int e = 1; e < NE; e++) if (l[e] > v1) { v1 = l[e]; i1 = e; }
        int i2 = -1; float v2 = -3.4e38f;
#pragma unroll
        for (int e = 0; e < NE; e++)
            if (e != i1 && l[e] > v2) { v2 = l[e]; i2 = e; }
        int p1 = atomicAdd(&g_cnt[i1], 1); g_tok[i1 * T_TOK + p1] = gw;
        int p2 = atomicAdd(&g_cnt[i2], 1); g_tok[i2 * T_TOK + p2] = gw;
        g_pe[2*gw] = i1; g_pp[2*gw] = p1;
        g_pe[2*gw+1] = i2; g_pp[2*gw+1] = p2;
    }
}

__global__ void offs_kernel() {
    if (blockIdx.x == 0 && threadIdx.x == 0) {
        int s = 0;
        for (int e = 0; e < NE; e++) { g_off[e] = s; s += g_cnt[e]; }
    }
}

__device__ __forceinline__ float gelu_exact(float v) {
    return 0.5f * v * (1.0f + erff(v * 0.70710678118654752440f));
}

// ---------------- tf32 mma.sync grouped GEMM -------------------------------
// CTA 128x128xBK(=16), 8 warps (2x4), warp tile 64x32, m16n8k8 fragments.
// 4-stage cp.async pipeline, 2 CTAs/SM (80KB dyn smem, <=128 regs).
// IS_G1: A = gathered g_xc rows, epilogue gelu(+b1)+tf32round -> g_h
// else : A = g_h rows,           epilogue raw                 -> g_y
template<int KTOT, bool IS_G1>
__global__ __launch_bounds__(256, 2) void gemm_tc(const float* __restrict__ bias_g) {
    const int e  = blockIdx.z;
    const int M  = g_cnt[e];
    const int m0 = blockIdx.x * BM;
    if (m0 >= M) return;
    const int n0   = blockIdx.y * BN;
    const int base = g_off[e];

    extern __shared__ __align__(128) char smem[];
    __shared__ float bias_s[BN];
    const uint32_t sb = s2u(smem);

    const int tid  = threadIdx.x;
    const int wid  = tid >> 5;
    const int lane = tid & 31;
    const int wm   = wid >> 2;            // 0..1 (m)
    const int wn   = wid & 3;             // 0..3 (n)
    const int ra   = lane >> 2;           // 0..7  (groupID)
    const int ca   = lane & 3;            // 0..3  (threadID_in_group)

    if (IS_G1 && tid < BN)
        bias_s[tid] = bias_g[(size_t)e * HID + n0 + tid];

    // g2s mapping: 2 threads per row, 2x16B chunks each (A and B same shape)
    const int arow = tid >> 1;            // 0..127
    const int aseg = tid & 1;             // half-row of 8 floats (32B)
    int ami = m0 + arow; if (ami > M - 1) ami = M - 1;   // clamp; masked at store
    const float* asrc;
    if (IS_G1) asrc = g_xc + (size_t)g_tok[e * T_TOK + ami] * EMB + aseg * 8;
    else       asrc = g_h  + (size_t)(base + ami) * HID + aseg * 8;
    const float* bsrc;
    if (IS_G1) bsrc = g_w1t + ((size_t)e * HID + n0 + arow) * (size_t)EMB + aseg * 8;
    else       bsrc = g_w2t + ((size_t)e * EMB + n0 + arow) * (size_t)HID + aseg * 8;

    const uint32_t dbase = arow * (PAD_ROW * 4) + aseg * 32;

#define LOAD_STAGE(kt_, s_) do {                                          \
        uint32_t st_ = sb + (s_) * STAGE_BYTES;                           \
        const float* as_ = asrc + (kt_) * BK;                             \
        const float* bs_ = bsrc + (kt_) * BK;                             \
        cp16(st_ + dbase,                as_);                            \
        cp16(st_ + dbase + 16,           as_ + 4);                        \
        cp16(st_ + A_BYTES + dbase,      bs_);                            \
        cp16(st_ + A_BYTES + dbase + 16, bs_ + 4);                        \
        CP_COMMIT();                                                      \
    } while (0)

    float acc[4][4][4];
#pragma unroll
    for (int mt = 0; mt < 4; mt++)
#pragma unroll
        for (int nt = 0; nt < 4; nt++)
#pragma unroll
            for (int q = 0; q < 4; q++) acc[mt][nt][q] = 0.f;

    const int NK = KTOT / BK;
    LOAD_STAGE(0, 0);
    LOAD_STAGE(1, 1);
    LOAD_STAGE(2, 2);

    for (int kt = 0; kt < NK; kt++) {
        const int cur = kt & (NSTAGE - 1);
        const int rem = NK - 1 - kt;
        if      (rem >= 2) cp_wait<2>();
        else if (rem == 1) cp_wait<1>();
        else               cp_wait<0>();
        __syncthreads();
        const int pf = kt + NSTAGE - 1;
        if (pf < NK) LOAD_STAGE(pf, pf & (NSTAGE - 1));

        const float* As = (const float*)(smem + cur * STAGE_BYTES);
        const float* Bs = (const float*)(smem + cur * STAGE_BYTES + A_BYTES);
#pragma unroll
        for (int kk = 0; kk < BK / 8; kk++) {
            uint32_t af[4][4];
#pragma unroll
            for (int mt = 0; mt < 4; mt++) {
                const float* p = As + (wm * 64 + mt * 16 + ra) * PAD_ROW + kk * 8 + ca;
                af[mt][0] = __float_as_uint(p[0]);
                af[mt][1] = __float_as_uint(p[8 * PAD_ROW]);
                af[mt][2] = __float_as_uint(p[4]);
                af[mt][3] = __float_as_uint(p[8 * PAD_ROW + 4]);
            }
            uint32_t bf[4][2];
#pragma unroll
            for (int nt = 0; nt < 4; nt++) {
                const float* p = Bs + (wn * 32 + nt * 8 + ra) * PAD_ROW + kk * 8 + ca;
                bf[nt][0] = __float_as_uint(p[0]);
                bf[nt][1] = __float_as_uint(p[4]);
            }
#pragma unroll
            for (int mt = 0; mt < 4; mt++)
#pragma unroll
                for (int nt = 0; nt < 4; nt++)
                    mma_tf32(acc[mt][nt], af[mt], bf[nt]);
        }
    }
#undef LOAD_STAGE

    // epilogue: acc[mt][nt] -> rows m0+wm*64+mt*16+ra(+8), cols n0+wn*32+nt*8+ca*2(+1)
#pragma unroll
    for (int mt = 0; mt < 4; mt++) {
#pragma unroll
        for (int half = 0; half < 2; half++) {
            const int m = m0 + wm * 64 + mt * 16 + ra + half * 8;
            if (m < M) {
                float* drow;
                if (IS_G1) drow = g_h + (size_t)(base + m) * HID + n0;
                else       drow = g_y + (size_t)(base + m) * EMB + n0;
#pragma unroll
                for (int nt = 0; nt < 4; nt++) {
                    const int c = wn * 32 + nt * 8 + ca * 2;
                    float v0 = acc[mt][nt][half * 2 + 0];
                    float v1 = acc[mt][nt][half * 2 + 1];
                    if (IS_G1) {
                        v0 = to_tf32(gelu_exact(v0 + bias_s[c]));
                        v1 = to_tf32(gelu_exact(v1 + bias_s[c + 1]));
                    }
                    *(float2*)(drow + c) = make_float2(v0, v1);
                }
            }
        }
    }
}

// ---------------- combine: out[t] = 0.5*(y[e1]+b2[e1] + y[e2]+b2[e2]) ------
__global__ void combine_kernel(const float* __restrict__ b2, float4* __restrict__ out) {
    int t  = blockIdx.x;
    int e1 = g_pe[2*t],     e2 = g_pe[2*t + 1];
    int r1 = g_off[e1] + g_pp[2*t];
    int r2 = g_off[e2] + g_pp[2*t + 1];
    const float4* y1 = (const float4*)(g_y + (size_t)r1 * EMB);
    const float4* y2 = (const float4*)(g_y + (size_t)r2 * EMB);
    const float4* c1 = (const float4*)(b2 + (size_t)e1 * EMB);
    const float4* c2 = (const float4*)(b2 + (size_t)e2 * EMB);
    float4* o = out + (size_t)t * (EMB / 4);
    int i = threadIdx.x;                       // EMB/4 == 256 == blockDim
    float4 a = y1[i], b = y2[i], p = c1[i], q = c2[i];
    o[i] = make_float4(0.5f * (a.x + b.x + p.x + q.x),
                       0.5f * (a.y + b.y + p.y + q.y),
                       0.5f * (a.z + b.z + p.z + q.z),
                       0.5f * (a.w + b.w + p.w + q.w));
}

// ---------------- launch ----------------------------------------------------
extern "C" void kernel_launch(void* const* d_in, const int* in_sizes, int n_in,
                              void* d_out, int out_size) {
    const float* x  = (const float*)d_in[0];
    const float* Wr = (const float*)d_in[1];
    const float* br = (const float*)d_in[2];
    const float* W1 = (const float*)d_in[3];
    const float* b1 = (const float*)d_in[4];
    const float* W2 = (const float*)d_in[5];
    const float* b2 = (const float*)d_in[6];
    float* out = (float*)d_out;

    // Not a stream op — safe under graph capture; called unconditionally.
    cudaFuncSetAttribute(gemm_tc<EMB, true>,
                         cudaFuncAttributeMaxDynamicSharedMemorySize, GEMM_SMEM);
    cudaFuncSetAttribute(gemm_tc<HID, false>,
                         cudaFuncAttributeMaxDynamicSharedMemorySize, GEMM_SMEM);

    prep_x_kernel<<<2048, 256>>>((const float4*)x, T_TOK * EMB / 4);
    transpose_kernel<0><<<dim3(HID/32, EMB/32, NE), dim3(32, 8)>>>(W1, EMB, HID);
    transpose_kernel<1><<<dim3(EMB/32, HID/32, NE), dim3(32, 8)>>>(W2, HID, EMB);
    router_kernel<<<T_TOK / 8, 256>>>(x, Wr, br);
    offs_kernel<<<1, 32>>>();
    gemm_tc<EMB, true ><<<dim3(T_TOK/BM, HID/BN, NE), 256, GEMM_SMEM>>>(b1);
    gemm_tc<HID, false><<<dim3(T_TOK/BM, EMB/BN, NE), 256, GEMM_SMEM>>>(b2);
    combine_kernel<<<T_TOK, 256>>>(b2, (float4*)out);
}